// round 14
// baseline (speedup 1.0000x reference)
#include <cuda_runtime.h>
#include <cstdint>

#define QM 8192
#define QK 4096
#define QN 4096

// GEMM: CTA 128x128. Warps 0-7: IMMA over K-stages [0,KS_T). Warps 8-15: dp4a
// over K-stages [KS_T,64). Each K-stage is 64 bytes of K.
// R13 post-mortem: superstages regressed -> tensor path reverted to R12.
// dp4a inner loop moved to v4 (16B) smem loads; predicted 2.9 -> ~2.35us/stage
// -> split 30/34.
#define KS_T 30
#define KS_D (64 - KS_T)

#define TILE_BYTES 8192u          // 128 rows x 64B per (tile, k-stage) block
#define SM_ROW 80u                // smem row stride
#define SM_TILE (128u * SM_ROW)   // 10240
#define SM_STAGE (2u * SM_TILE)   // A + B = 20480
#define RINGT_BYTES (4u * SM_STAGE)             // 81920 (holds cbuf 67584 + rowbuf)
#define SMEM_TOTAL (RINGT_BYTES + 3u * SM_STAGE) // 143360
#define ROWBUF_OFF 67584u         // after cbuf, inside ring-T space

// ---------------- device scratch (static allocation is allowed) -------------
__device__ __align__(256) int8_t g_A[(size_t)QM * QK];
__device__ __align__(256) int8_t g_B[(size_t)QN * QK];
__device__ float g_ts[QM];
__device__ float g_zp[QM];
__device__ float g_qsum[QM];
__device__ float g_wrs[QN];
__device__ int g_wmode;    // 0 = int8 buffer, 1 = int32 buffer, 2 = float32 buffer
__device__ int g_swapsz;   // 1 if d_in[2] actually holds zeros (swapped)

// ---------------- PTX helpers ----------------------------------------------
__device__ __forceinline__ uint32_t smem_u32(const void* p) {
    uint32_t a;
    asm("{ .reg .u64 t; cvta.to.shared.u64 t, %1; cvt.u32.u64 %0, t; }"
        : "=r"(a) : "l"(p));
    return a;
}

#define CP_ASYNC16(dst, src) \
    asm volatile("cp.async.cg.shared.global [%0], [%1], 16;" \
                 :: "r"(dst), "l"(src) : "memory")
#define CP_COMMIT() asm volatile("cp.async.commit_group;" ::: "memory")
#define CP_WAIT2()  asm volatile("cp.async.wait_group 2;" ::: "memory")
#define CP_WAIT1()  asm volatile("cp.async.wait_group 1;" ::: "memory")

#define LDS128(r0, r1, r2, r3, a) \
    asm volatile("ld.shared.v4.u32 {%0,%1,%2,%3}, [%4];" \
        : "=r"(r0), "=r"(r1), "=r"(r2), "=r"(r3) : "r"(a))

#define LDSM4(r0, r1, r2, r3, a) \
    asm volatile("ldmatrix.sync.aligned.m8n8.x4.shared.b16 {%0,%1,%2,%3}, [%4];" \
        : "=r"(r0), "=r"(r1), "=r"(r2), "=r"(r3) : "r"(a))

#define BAR_T() asm volatile("bar.sync 1, 256;" ::: "memory")
#define BAR_D() asm volatile("bar.sync 2, 256;" ::: "memory")

#define IMMA(c, a, b) \
    asm volatile("mma.sync.aligned.m16n8k32.row.col.s32.s8.s8.s32 " \
        "{%0,%1,%2,%3}, {%4,%5,%6,%7}, {%8,%9}, {%0,%1,%2,%3};" \
        : "+r"((c)[0]), "+r"((c)[1]), "+r"((c)[2]), "+r"((c)[3]) \
        : "r"((a)[0]), "r"((a)[1]), "r"((a)[2]), "r"((a)[3]), \
          "r"((b)[0]), "r"((b)[1]))

// ================= kernel 0: input-format detection =========================
__global__ void __launch_bounds__(256) detect_kernel(const uint32_t* __restrict__ w,
                                                     const float* __restrict__ p2) {
    __shared__ int not_i32, not_f32, p2_bad;
    if (threadIdx.x == 0) { not_i32 = 0; not_f32 = 0; p2_bad = 0; }
    __syncthreads();
    int ni = 0, nf = 0;
    for (int i = threadIdx.x; i < 4096; i += 256) {
        const uint32_t u = w[i];
        const int v = (int)u;
        if (!(v >= -128 && v <= 127)) ni++;
        const float f = __uint_as_float(u);
        if (!(isfinite(f) && fabsf(f) <= 128.0f && f == rintf(f))) nf++;
    }
    if (ni) atomicAdd(&not_i32, ni);
    if (nf) atomicAdd(&not_f32, nf);
    {
        const float s = p2[threadIdx.x * 16];
        if (!(s > 0.0f && s < 0.03f)) atomicAdd(&p2_bad, 1);
    }
    __syncthreads();
    if (threadIdx.x == 0) {
        g_wmode = (not_i32 == 0) ? 1 : ((not_f32 == 0) ? 2 : 0);
        g_swapsz = (p2_bad > 0) ? 1 : 0;
    }
}

// ================= kernel 1: per-token dynamic quant ========================
__device__ __forceinline__ int q_one(float v, float scale, float zp) {
    float t = rintf(__fdiv_rn(v, scale)) + zp;
    t = fminf(fmaxf(t, -128.0f), 127.0f);
    return (int)t;
}

__global__ void __launch_bounds__(256) quant_kernel(const float* __restrict__ x) {
    const int m = blockIdx.x;
    const int tid = threadIdx.x;
    const int lane = tid & 31, wid = tid >> 5;

    const float4* xr = reinterpret_cast<const float4*>(x) + (size_t)m * (QK / 4);
    float4 v[4];
    float mn = 0.0f, mx = 0.0f;
#pragma unroll
    for (int i = 0; i < 4; i++) {
        v[i] = xr[i * 256 + tid];
        mn = fminf(mn, fminf(fminf(v[i].x, v[i].y), fminf(v[i].z, v[i].w)));
        mx = fmaxf(mx, fmaxf(fmaxf(v[i].x, v[i].y), fmaxf(v[i].z, v[i].w)));
    }
#pragma unroll
    for (int o = 16; o; o >>= 1) {
        mn = fminf(mn, __shfl_xor_sync(0xffffffffu, mn, o));
        mx = fmaxf(mx, __shfl_xor_sync(0xffffffffu, mx, o));
    }
    __shared__ float smn[8], smx[8], s_scale, s_zp;
    __shared__ int s_qs;
    if (lane == 0) { smn[wid] = mn; smx[wid] = mx; }
    __syncthreads();
    if (tid == 0) {
        float a = smn[0], b = smx[0];
#pragma unroll
        for (int i = 1; i < 8; i++) { a = fminf(a, smn[i]); b = fmaxf(b, smx[i]); }
        float scale = fmaxf(__fdiv_rn(b - a, 255.0f), 1.1920928955078125e-07f);
        float zp = fminf(fmaxf(-128.0f - rintf(__fdiv_rn(a, scale)), -128.0f), 127.0f);
        s_scale = scale; s_zp = zp; s_qs = 0;
        g_ts[m] = scale;
        g_zp[m] = zp;
    }
    __syncthreads();
    const float scale = s_scale, zp = s_zp;
    int qs = 0;
    const size_t mtbase = (size_t)(m >> 7) * 64 * TILE_BYTES + (size_t)(m & 127) * 64;
#pragma unroll
    for (int i = 0; i < 4; i++) {
        const int k = (i * 256 + tid) * 4;
        int q0 = q_one(v[i].x, scale, zp);
        int q1 = q_one(v[i].y, scale, zp);
        int q2 = q_one(v[i].z, scale, zp);
        int q3 = q_one(v[i].w, scale, zp);
        qs += q0 + q1 + q2 + q3;
        char4 c4 = make_char4((char)q0, (char)q1, (char)q2, (char)q3);
        size_t pos = mtbase + (size_t)(k >> 6) * TILE_BYTES + (size_t)(k & 63);
        *reinterpret_cast<char4*>(g_A + pos) = c4;
    }
#pragma unroll
    for (int o = 16; o; o >>= 1) qs += __shfl_xor_sync(0xffffffffu, qs, o);
    if (lane == 0) atomicAdd(&s_qs, qs);
    __syncthreads();
    if (tid == 0) g_qsum[m] = (float)s_qs;
}

// ================= kernel 2: weight pre-tiling + row sums ===================
__global__ void __launch_bounds__(256) wprep_kernel(const void* __restrict__ wbuf) {
    const int o = blockIdx.x, tid = threadIdx.x;
    const int lane = tid & 31, wid = tid >> 5;
    const int mode = g_wmode;

    int4 v;
    if (mode == 0) {
        v = reinterpret_cast<const int4*>(wbuf)[(size_t)o * 256 + tid];
    } else {
        char tmp[16];
        if (mode == 1) {
            const int* p = reinterpret_cast<const int*>(wbuf) + (size_t)o * QK + tid * 16;
#pragma unroll
            for (int j = 0; j < 16; j++) tmp[j] = (char)p[j];
        } else {
            const float* p = reinterpret_cast<const float*>(wbuf) + (size_t)o * QK + tid * 16;
#pragma unroll
            for (int j = 0; j < 16; j++) tmp[j] = (char)(int)p[j];
        }
        v = *reinterpret_cast<const int4*>(tmp);
    }

    int s = 0;
    s = __dp4a(v.x, 0x01010101, s);
    s = __dp4a(v.y, 0x01010101, s);
    s = __dp4a(v.z, 0x01010101, s);
    s = __dp4a(v.w, 0x01010101, s);
    size_t pos = ((size_t)(o >> 7) * 64 + (size_t)(tid >> 2)) * TILE_BYTES
               + (size_t)(o & 127) * 64 + (size_t)(tid & 3) * 16;
    *reinterpret_cast<int4*>(g_B + pos) = v;

    __shared__ int sw[8];
#pragma unroll
    for (int t = 16; t; t >>= 1) s += __shfl_xor_sync(0xffffffffu, s, t);
    if (lane == 0) sw[wid] = s;
    __syncthreads();
    if (tid == 0) {
        int tot = 0;
#pragma unroll
        for (int i = 0; i < 8; i++) tot += sw[i];
        g_wrs[o] = (float)tot;
    }
}

// ================= kernel 3: hybrid IMMA + dp4a GEMM ========================
__global__ void __launch_bounds__(512, 1)
gemm_kernel(const float* __restrict__ in2, const float* __restrict__ in3,
            float* __restrict__ out) {
    extern __shared__ __align__(128) char smem[];
    const uint32_t sbase = smem_u32(smem);
    const uint32_t dbase = sbase + RINGT_BYTES;
    const int tid = threadIdx.x;
    const int lane = tid & 31, wid = tid >> 5;
    const int nt = blockIdx.x & 31;   // n fastest -> wave reuses A tiles in L2
    const int mt = blockIdx.x >> 5;

    int* cbuf = reinterpret_cast<int*>(smem);   // 128 x 132 ints, in ring-T space
    float* rowp = reinterpret_cast<float*>(smem + ROWBUF_OFF); // [ts|zp|A1] x128

    if (wid < 8) {
        // ================== tensor group: warps 0-7, K-stages [0, KS_T) =====
        const int wm = wid >> 2, wn = wid & 3;
        const int rr = lane >> 2, q = lane & 3;

        // ldmatrix lane offset: rows (lane&15), +16B for upper half-warp
        const uint32_t lsm_off = (uint32_t)(lane & 15) * SM_ROW
                               + (uint32_t)(lane >> 4) * 16u;

        int c[4][4][4];
#pragma unroll
        for (int mi = 0; mi < 4; mi++)
#pragma unroll
            for (int ni = 0; ni < 4; ni++)
#pragma unroll
                for (int r = 0; r < 4; r++) c[mi][ni][r] = 0;

        auto issueT = [&](int ks) {
            const int s = ks & 3;
            const int8_t* gA = g_A + ((size_t)(mt * 64 + ks)) * TILE_BYTES;
            const int8_t* gB = g_B + ((size_t)(nt * 64 + ks)) * TILE_BYTES;
            const uint32_t dA = sbase + s * SM_STAGE;
            const uint32_t dB = dA + SM_TILE;
#pragma unroll
            for (int i = 0; i < 2; i++) {
                const int idx = tid + i * 256;
                const uint32_t off = (uint32_t)(idx >> 2) * SM_ROW + (uint32_t)(idx & 3) * 16;
                CP_ASYNC16(dA + off, gA + (size_t)idx * 16);
                CP_ASYNC16(dB + off, gB + (size_t)idx * 16);
            }
            CP_COMMIT();
        };

        issueT(0); issueT(1); issueT(2);

#pragma unroll 1
        for (int ks = 0; ks < KS_T; ks++) {
            CP_WAIT2();
            BAR_T();
            if (ks + 3 < KS_T) issueT(ks + 3); else CP_COMMIT();

            const uint32_t ast = sbase + (ks & 3) * SM_STAGE;
            const uint32_t bst = ast + SM_TILE;
#pragma unroll
            for (int kj = 0; kj < 2; kj++) {
                uint32_t a[4][4], b[4][2];
#pragma unroll
                for (int mi = 0; mi < 4; mi++)
                    LDSM4(a[mi][0], a[mi][1], a[mi][2], a[mi][3],
                          ast + (uint32_t)(wm * 64 + mi * 16) * SM_ROW
                              + (uint32_t)(kj * 32) + lsm_off);
                // B: one x4 covers 2 ni (16 rows) x both k-halves
                LDSM4(b[0][0], b[1][0], b[0][1], b[1][1],
                      bst + (uint32_t)(wn * 32) * SM_ROW
                          + (uint32_t)(kj * 32) + lsm_off);
                LDSM4(b[2][0], b[3][0], b[2][1], b[3][1],
                      bst + (uint32_t)(wn * 32 + 16) * SM_ROW
                          + (uint32_t)(kj * 32) + lsm_off);
#pragma unroll
                for (int mi = 0; mi < 4; mi++)
#pragma unroll
                    for (int ni = 0; ni < 4; ni++)
                        IMMA(c[mi][ni], a[mi], b[ni]);
            }
        }

        // all tensor warps done reading ring T -> safe to overwrite with cbuf
        BAR_T();
#pragma unroll
        for (int mi = 0; mi < 4; mi++)
#pragma unroll
            for (int half = 0; half < 2; half++) {
                const int rl = wm * 64 + mi * 16 + rr + half * 8;
#pragma unroll
                for (int ni = 0; ni < 4; ni++) {
                    const int cl = wn * 32 + ni * 8 + q * 2;
                    cbuf[rl * 132 + cl]     = c[mi][ni][half * 2 + 0];
                    cbuf[rl * 132 + cl + 1] = c[mi][ni][half * 2 + 1];
                }
            }
        __syncthreads();   // hand cbuf to dp4a group

        // tensor warps are otherwise idle here: stage row params for epilogue
        if (tid < 128) {
            const int row = mt * 128 + tid;
            const float ts = g_ts[row];
            const float zp = g_zp[row];
            rowp[tid]       = ts;
            rowp[128 + tid] = zp;
            rowp[256 + tid] = g_qsum[row] - 4096.0f * zp;
        }
        __syncthreads();   // wait for dp4a partials merged + rowbuf visible
    } else {
        // ================== dp4a group: warps 8-15, K-stages [KS_T, 64) =====
        // smem rows swizzled at 16B: row r lives at r*80 + 16*((r>>3)&1)
        const int dw = wid - 8;           // 0..7 -> rows dw*16 .. dw*16+15
        const int rg = lane >> 4;         // 0..1
        const int cg = lane & 15;         // cols cg + 16*j
        const int t2 = tid - 256;

        int acc[8][8];
#pragma unroll
        for (int i = 0; i < 8; i++)
#pragma unroll
            for (int j = 0; j < 8; j++) acc[i][j] = 0;

        auto issueD = [&](int kd) {
            const int s = kd % 3;
            const int ks = KS_T + kd;
            const int8_t* gA = g_A + ((size_t)(mt * 64 + ks)) * TILE_BYTES;
            const int8_t* gB = g_B + ((size_t)(nt * 64 + ks)) * TILE_BYTES;
            const uint32_t dA = dbase + s * SM_STAGE;
            const uint32_t dB = dA + SM_TILE;
#pragma unroll
            for (int i = 0; i < 2; i++) {
                const int idx = t2 + i * 256;          // 16B chunk id, 0..511
                const uint32_t row = (uint32_t)(idx >> 2);
                const uint32_t off = row * SM_ROW + (((row >> 3) & 1u) << 4)
                                   + (uint32_t)(idx & 3) * 16;
                CP_ASYNC16(dA + off, gA + (size_t)idx * 16);
                CP_ASYNC16(dB + off, gB + (size_t)idx * 16);
            }
            CP_COMMIT();
        };

        issueD(0); issueD(1);

        const uint32_t aswz = (uint32_t)rg * 16u;              // rows dw*16+rg*8+i
        const uint32_t bswz = (uint32_t)((cg >> 3) & 1) * 16u; // rows cg+16*j

#pragma unroll 1
        for (int kd = 0; kd < KS_D; kd++) {
            CP_WAIT1();
            BAR_D();
            if (kd + 2 < KS_D) issueD(kd + 2); else CP_COMMIT();

            const uint32_t ast = dbase + (kd % 3) * SM_STAGE;
            const uint32_t arow = ast + (uint32_t)(dw * 16 + rg * 8) * SM_ROW + aswz;
            const uint32_t brow = ast + SM_TILE + (uint32_t)cg * SM_ROW + bswz;
#pragma unroll
            for (int kb = 0; kb < 4; kb++) {     // 16B of K per iteration
                uint32_t a[8][4];
#pragma unroll
                for (int i = 0; i < 8; i++)
                    LDS128(a[i][0], a[i][1], a[i][2], a[i][3],
                           arow + i * SM_ROW + kb * 16);
                // j-loop split in halves of 4: caps live B regs at 16
#pragma unroll
                for (int jh = 0; jh < 2; jh++) {
                    uint32_t b[4][4];
#pragma unroll
                    for (int j2 = 0; j2 < 4; j2++)
                        LDS128(b[j2][0], b[j2][1], b[j2][2], b[j2][3],
                               brow + (uint32_t)((jh * 4 + j2) * 16) * SM_ROW + kb * 16);
#pragma unroll
                    for (int i = 0; i < 8; i++)
#pragma unroll
                        for (int j2 = 0; j2 < 4; j2++) {
                            int s_ = acc[i][jh * 4 + j2];
                            s_ = __dp4a((int)a[i][0], (int)b[j2][0], s_);
                            s_ = __dp4a((int)a[i][1], (int)b[j2][1], s_);
                            s_ = __dp4a((int)a[i][2], (int)b[j2][2], s_);
                            s_ = __dp4a((int)a[i][3], (int)b[j2][3], s_);
                            acc[i][jh * 4 + j2] = s_;
                        }
                }
            }
        }

        __syncthreads();   // wait for cbuf from tensor group

        // merge dp4a partials into cbuf (each element owned by one thread)
#pragma unroll
        for (int i = 0; i < 8; i++) {
            const int rl = dw * 16 + rg * 8 + i;
#pragma unroll
            for (int j = 0; j < 8; j++)
                cbuf[rl * 132 + cg + 16 * j] += acc[i][j];
        }
        __syncthreads();   // totals + rowbuf ready for everyone
    }

    // ================== epilogue: all 512 threads ===========================
    const int swp = g_swapsz;
    const float* scv = swp ? in3 : in2;   // true scales
    const float* zrv = swp ? in2 : in3;   // true zeros

    // col is loop-invariant per thread: e&127 == tid&127 (512 % 128 == 0)
    const int cc = tid & 127;
    const int c0 = tid >> 7;              // 0..3
    const int col = nt * 128 + cc;
    const float sc = scv[col];
    const float zr = zrv[col];
    const float wr = g_wrs[col];
    float* ocol = out + (size_t)(mt * 128) * QN + col;

#pragma unroll 4
    for (int j = 0; j < 32; j++) {
        const int r = 4 * j + c0;
        const float ts = rowp[r];
        const float zp = rowp[128 + r];
        const float A1 = rowp[256 + r];
        const float tot = (float)cbuf[r * 132 + cc];
        ocol[(size_t)r * QN] = ts * sc * (tot - zp * wr - zr * A1);
    }
}

// ================= launch ===================================================
extern "C" void kernel_launch(void* const* d_in, const int* in_sizes, int n_in,
                              void* d_out, int out_size) {
    const float* x    = (const float*)d_in[0];
    const void*  wbuf = d_in[1];
    const float* in2  = (const float*)d_in[2];
    const float* in3  = (const float*)d_in[3];
    float* out = (float*)d_out;

    cudaFuncSetAttribute(gemm_kernel, cudaFuncAttributeMaxDynamicSharedMemorySize,
                         (int)SMEM_TOTAL);

    detect_kernel<<<1, 256>>>((const uint32_t*)wbuf, in2);
    quant_kernel<<<QM, 256>>>(x);
    wprep_kernel<<<QN, 256>>>(wbuf);
    gemm_kernel<<<(QM / 128) * (QN / 128), 512, SMEM_TOTAL>>>(in2, in3, out);
}

// round 15
// speedup vs baseline: 1.0367x; 1.0367x over previous
#include <cuda_runtime.h>
#include <cstdint>

#define QM 8192
#define QK 4096
#define QN 4096

// GEMM: CTA 128x128. Warps 8-15 (HIGH arbiter priority): IMMA over K-stages
// [0,KS_T), 5-slot ring, 4 copies in flight. Warps 0-7: dp4a over [KS_T,64).
// R14 post-mortem: dp4a pinned at pipe floor ~2.93us/stage; tensor idle is
// issue starvation (hi-wid-first arbiter) -> swap groups. Split 35/29.
#define KS_T 35
#define KS_D (64 - KS_T)

#define TILE_BYTES 8192u          // 128 rows x 64B per (tile, k-stage) block
#define SM_ROW 80u                // smem row stride
#define SM_TILE (128u * SM_ROW)   // 10240
#define SM_STAGE (2u * SM_TILE)   // A + B = 20480
#define RINGT_BYTES (5u * SM_STAGE)             // 102400 (holds cbuf + rowbuf)
#define SMEM_TOTAL (RINGT_BYTES + 3u * SM_STAGE) // 163840
#define ROWBUF_OFF 67584u         // after cbuf, inside ring-T space

// ---------------- device scratch (static allocation is allowed) -------------
__device__ __align__(256) int8_t g_A[(size_t)QM * QK];
__device__ __align__(256) int8_t g_B[(size_t)QN * QK];
__device__ float g_ts[QM];
__device__ float g_zp[QM];
__device__ float g_qsum[QM];
__device__ float g_wrs[QN];
__device__ int g_wmode;    // 0 = int8 buffer, 1 = int32 buffer, 2 = float32 buffer
__device__ int g_swapsz;   // 1 if d_in[2] actually holds zeros (swapped)

// ---------------- PTX helpers ----------------------------------------------
__device__ __forceinline__ uint32_t smem_u32(const void* p) {
    uint32_t a;
    asm("{ .reg .u64 t; cvta.to.shared.u64 t, %1; cvt.u32.u64 %0, t; }"
        : "=r"(a) : "l"(p));
    return a;
}

#define CP_ASYNC16(dst, src) \
    asm volatile("cp.async.cg.shared.global [%0], [%1], 16;" \
                 :: "r"(dst), "l"(src) : "memory")
#define CP_ASYNC8(dst, src) \
    asm volatile("cp.async.ca.shared.global [%0], [%1], 8;" \
                 :: "r"(dst), "l"(src) : "memory")
#define CP_COMMIT() asm volatile("cp.async.commit_group;" ::: "memory")
#define CP_WAIT3()  asm volatile("cp.async.wait_group 3;" ::: "memory")
#define CP_WAIT1()  asm volatile("cp.async.wait_group 1;" ::: "memory")

#define LDS64(r0, r1, a) \
    asm volatile("ld.shared.v2.u32 {%0,%1}, [%2];" : "=r"(r0), "=r"(r1) : "r"(a))

#define LDSM4(r0, r1, r2, r3, a) \
    asm volatile("ldmatrix.sync.aligned.m8n8.x4.shared.b16 {%0,%1,%2,%3}, [%4];" \
        : "=r"(r0), "=r"(r1), "=r"(r2), "=r"(r3) : "r"(a))

#define BAR_T() asm volatile("bar.sync 1, 256;" ::: "memory")
#define BAR_D() asm volatile("bar.sync 2, 256;" ::: "memory")

#define IMMA(c, a, b) \
    asm volatile("mma.sync.aligned.m16n8k32.row.col.s32.s8.s8.s32 " \
        "{%0,%1,%2,%3}, {%4,%5,%6,%7}, {%8,%9}, {%0,%1,%2,%3};" \
        : "+r"((c)[0]), "+r"((c)[1]), "+r"((c)[2]), "+r"((c)[3]) \
        : "r"((a)[0]), "r"((a)[1]), "r"((a)[2]), "r"((a)[3]), \
          "r"((b)[0]), "r"((b)[1]))

// ================= kernel 0: input-format detection =========================
__global__ void __launch_bounds__(256) detect_kernel(const uint32_t* __restrict__ w,
                                                     const float* __restrict__ p2) {
    __shared__ int not_i32, not_f32, p2_bad;
    if (threadIdx.x == 0) { not_i32 = 0; not_f32 = 0; p2_bad = 0; }
    __syncthreads();
    int ni = 0, nf = 0;
    for (int i = threadIdx.x; i < 4096; i += 256) {
        const uint32_t u = w[i];
        const int v = (int)u;
        if (!(v >= -128 && v <= 127)) ni++;
        const float f = __uint_as_float(u);
        if (!(isfinite(f) && fabsf(f) <= 128.0f && f == rintf(f))) nf++;
    }
    if (ni) atomicAdd(&not_i32, ni);
    if (nf) atomicAdd(&not_f32, nf);
    {
        const float s = p2[threadIdx.x * 16];
        if (!(s > 0.0f && s < 0.03f)) atomicAdd(&p2_bad, 1);
    }
    __syncthreads();
    if (threadIdx.x == 0) {
        g_wmode = (not_i32 == 0) ? 1 : ((not_f32 == 0) ? 2 : 0);
        g_swapsz = (p2_bad > 0) ? 1 : 0;
    }
}

// ================= kernel 1: per-token dynamic quant ========================
__device__ __forceinline__ int q_one(float v, float scale, float zp) {
    float t = rintf(__fdiv_rn(v, scale)) + zp;
    t = fminf(fmaxf(t, -128.0f), 127.0f);
    return (int)t;
}

__global__ void __launch_bounds__(256) quant_kernel(const float* __restrict__ x) {
    const int m = blockIdx.x;
    const int tid = threadIdx.x;
    const int lane = tid & 31, wid = tid >> 5;

    const float4* xr = reinterpret_cast<const float4*>(x) + (size_t)m * (QK / 4);
    float4 v[4];
    float mn = 0.0f, mx = 0.0f;
#pragma unroll
    for (int i = 0; i < 4; i++) {
        v[i] = xr[i * 256 + tid];
        mn = fminf(mn, fminf(fminf(v[i].x, v[i].y), fminf(v[i].z, v[i].w)));
        mx = fmaxf(mx, fmaxf(fmaxf(v[i].x, v[i].y), fmaxf(v[i].z, v[i].w)));
    }
#pragma unroll
    for (int o = 16; o; o >>= 1) {
        mn = fminf(mn, __shfl_xor_sync(0xffffffffu, mn, o));
        mx = fmaxf(mx, __shfl_xor_sync(0xffffffffu, mx, o));
    }
    __shared__ float smn[8], smx[8], s_scale, s_zp;
    __shared__ int s_qs;
    if (lane == 0) { smn[wid] = mn; smx[wid] = mx; }
    __syncthreads();
    if (tid == 0) {
        float a = smn[0], b = smx[0];
#pragma unroll
        for (int i = 1; i < 8; i++) { a = fminf(a, smn[i]); b = fmaxf(b, smx[i]); }
        float scale = fmaxf(__fdiv_rn(b - a, 255.0f), 1.1920928955078125e-07f);
        float zp = fminf(fmaxf(-128.0f - rintf(__fdiv_rn(a, scale)), -128.0f), 127.0f);
        s_scale = scale; s_zp = zp; s_qs = 0;
        g_ts[m] = scale;
        g_zp[m] = zp;
    }
    __syncthreads();
    const float scale = s_scale, zp = s_zp;
    int qs = 0;
    const size_t mtbase = (size_t)(m >> 7) * 64 * TILE_BYTES + (size_t)(m & 127) * 64;
#pragma unroll
    for (int i = 0; i < 4; i++) {
        const int k = (i * 256 + tid) * 4;
        int q0 = q_one(v[i].x, scale, zp);
        int q1 = q_one(v[i].y, scale, zp);
        int q2 = q_one(v[i].z, scale, zp);
        int q3 = q_one(v[i].w, scale, zp);
        qs += q0 + q1 + q2 + q3;
        char4 c4 = make_char4((char)q0, (char)q1, (char)q2, (char)q3);
        size_t pos = mtbase + (size_t)(k >> 6) * TILE_BYTES + (size_t)(k & 63);
        *reinterpret_cast<char4*>(g_A + pos) = c4;
    }
#pragma unroll
    for (int o = 16; o; o >>= 1) qs += __shfl_xor_sync(0xffffffffu, qs, o);
    if (lane == 0) atomicAdd(&s_qs, qs);
    __syncthreads();
    if (tid == 0) g_qsum[m] = (float)s_qs;
}

// ================= kernel 2: weight pre-tiling + row sums ===================
__global__ void __launch_bounds__(256) wprep_kernel(const void* __restrict__ wbuf) {
    const int o = blockIdx.x, tid = threadIdx.x;
    const int lane = tid & 31, wid = tid >> 5;
    const int mode = g_wmode;

    int4 v;
    if (mode == 0) {
        v = reinterpret_cast<const int4*>(wbuf)[(size_t)o * 256 + tid];
    } else {
        char tmp[16];
        if (mode == 1) {
            const int* p = reinterpret_cast<const int*>(wbuf) + (size_t)o * QK + tid * 16;
#pragma unroll
            for (int j = 0; j < 16; j++) tmp[j] = (char)p[j];
        } else {
            const float* p = reinterpret_cast<const float*>(wbuf) + (size_t)o * QK + tid * 16;
#pragma unroll
            for (int j = 0; j < 16; j++) tmp[j] = (char)(int)p[j];
        }
        v = *reinterpret_cast<const int4*>(tmp);
    }

    int s = 0;
    s = __dp4a(v.x, 0x01010101, s);
    s = __dp4a(v.y, 0x01010101, s);
    s = __dp4a(v.z, 0x01010101, s);
    s = __dp4a(v.w, 0x01010101, s);
    size_t pos = ((size_t)(o >> 7) * 64 + (size_t)(tid >> 2)) * TILE_BYTES
               + (size_t)(o & 127) * 64 + (size_t)(tid & 3) * 16;
    *reinterpret_cast<int4*>(g_B + pos) = v;

    __shared__ int sw[8];
#pragma unroll
    for (int t = 16; t; t >>= 1) s += __shfl_xor_sync(0xffffffffu, s, t);
    if (lane == 0) sw[wid] = s;
    __syncthreads();
    if (tid == 0) {
        int tot = 0;
#pragma unroll
        for (int i = 0; i < 8; i++) tot += sw[i];
        g_wrs[o] = (float)tot;
    }
}

// ================= kernel 3: hybrid IMMA + dp4a GEMM ========================
__global__ void __launch_bounds__(512, 1)
gemm_kernel(const float* __restrict__ in2, const float* __restrict__ in3,
            float* __restrict__ out) {
    extern __shared__ __align__(128) char smem[];
    const uint32_t sbase = smem_u32(smem);
    const uint32_t dbase = sbase + RINGT_BYTES;
    const int tid = threadIdx.x;
    const int lane = tid & 31, wid = tid >> 5;
    const int nt = blockIdx.x & 31;   // n fastest -> wave reuses A tiles in L2
    const int mt = blockIdx.x >> 5;

    int* cbuf = reinterpret_cast<int*>(smem);   // 128 x 132 ints, in ring-T space
    float* rowp = reinterpret_cast<float*>(smem + ROWBUF_OFF); // [ts|zp|A1] x128

    if (wid >= 8) {
        // == tensor group: warps 8-15 (hi arbiter priority), stages [0,KS_T) ==
        const int tw = wid - 8;
        const int wm = tw >> 2, wn = tw & 3;
        const int rr = lane >> 2, q = lane & 3;
        const int t2 = tid - 256;

        // ldmatrix lane offset: rows (lane&15), +16B for upper half-warp
        const uint32_t lsm_off = (uint32_t)(lane & 15) * SM_ROW
                               + (uint32_t)(lane >> 4) * 16u;

        int c[4][4][4];
#pragma unroll
        for (int mi = 0; mi < 4; mi++)
#pragma unroll
            for (int ni = 0; ni < 4; ni++)
#pragma unroll
                for (int r = 0; r < 4; r++) c[mi][ni][r] = 0;

        auto issueT = [&](int ks) {
            const int s = ks % 5;
            const int8_t* gA = g_A + ((size_t)(mt * 64 + ks)) * TILE_BYTES;
            const int8_t* gB = g_B + ((size_t)(nt * 64 + ks)) * TILE_BYTES;
            const uint32_t dA = sbase + s * SM_STAGE;
            const uint32_t dB = dA + SM_TILE;
#pragma unroll
            for (int i = 0; i < 2; i++) {
                const int idx = t2 + i * 256;
                const uint32_t off = (uint32_t)(idx >> 2) * SM_ROW + (uint32_t)(idx & 3) * 16;
                CP_ASYNC16(dA + off, gA + (size_t)idx * 16);
                CP_ASYNC16(dB + off, gB + (size_t)idx * 16);
            }
            CP_COMMIT();
        };

        issueT(0); issueT(1); issueT(2); issueT(3);

#pragma unroll 1
        for (int ks = 0; ks < KS_T; ks++) {
            CP_WAIT3();
            BAR_T();
            if (ks + 4 < KS_T) issueT(ks + 4); else CP_COMMIT();

            const uint32_t ast = sbase + (ks % 5) * SM_STAGE;
            const uint32_t bst = ast + SM_TILE;
#pragma unroll
            for (int kj = 0; kj < 2; kj++) {
                uint32_t a[4][4], b[4][2];
#pragma unroll
                for (int mi = 0; mi < 4; mi++)
                    LDSM4(a[mi][0], a[mi][1], a[mi][2], a[mi][3],
                          ast + (uint32_t)(wm * 64 + mi * 16) * SM_ROW
                              + (uint32_t)(kj * 32) + lsm_off);
                // B: one x4 covers 2 ni (16 rows) x both k-halves
                LDSM4(b[0][0], b[1][0], b[0][1], b[1][1],
                      bst + (uint32_t)(wn * 32) * SM_ROW
                          + (uint32_t)(kj * 32) + lsm_off);
                LDSM4(b[2][0], b[3][0], b[2][1], b[3][1],
                      bst + (uint32_t)(wn * 32 + 16) * SM_ROW
                          + (uint32_t)(kj * 32) + lsm_off);
#pragma unroll
                for (int mi = 0; mi < 4; mi++)
#pragma unroll
                    for (int ni = 0; ni < 4; ni++)
                        IMMA(c[mi][ni], a[mi], b[ni]);
            }
        }

        // all tensor warps done reading ring T -> safe to overwrite with cbuf
        BAR_T();
#pragma unroll
        for (int mi = 0; mi < 4; mi++)
#pragma unroll
            for (int half = 0; half < 2; half++) {
                const int rl = wm * 64 + mi * 16 + rr + half * 8;
#pragma unroll
                for (int ni = 0; ni < 4; ni++) {
                    const int cl = wn * 32 + ni * 8 + q * 2;
                    cbuf[rl * 132 + cl]     = c[mi][ni][half * 2 + 0];
                    cbuf[rl * 132 + cl + 1] = c[mi][ni][half * 2 + 1];
                }
            }
        __syncthreads();   // hand cbuf to dp4a group

        // tensor warps are otherwise idle here: stage row params for epilogue
        if (t2 < 128) {
            const int row = mt * 128 + t2;
            const float ts = g_ts[row];
            const float zp = g_zp[row];
            rowp[t2]       = ts;
            rowp[128 + t2] = zp;
            rowp[256 + t2] = g_qsum[row] - 4096.0f * zp;
        }
        __syncthreads();   // wait for dp4a partials merged + rowbuf visible
    } else {
        // ========= dp4a group: warps 0-7, K-stages [KS_T, 64) ===============
        // smem rows swizzled: row r lives at r*80 + 8*((r>>3)&1) (conflict-free)
        const int dw = wid;               // 0..7 -> rows dw*16 .. dw*16+15
        const int rg = lane >> 4;         // 0..1
        const int cg = lane & 15;         // cols cg + 16*j

        int acc[8][8];
#pragma unroll
        for (int i = 0; i < 8; i++)
#pragma unroll
            for (int j = 0; j < 8; j++) acc[i][j] = 0;

        auto issueD = [&](int kd) {
            const int s = kd % 3;
            const int ks = KS_T + kd;
            const int8_t* gA = g_A + ((size_t)(mt * 64 + ks)) * TILE_BYTES;
            const int8_t* gB = g_B + ((size_t)(nt * 64 + ks)) * TILE_BYTES;
            const uint32_t dA = dbase + s * SM_STAGE;
            const uint32_t dB = dA + SM_TILE;
#pragma unroll
            for (int i = 0; i < 4; i++) {
                const int idx = tid + i * 256;         // 8B chunk id, 0..1023
                const uint32_t row = (uint32_t)(idx >> 3);
                const uint32_t off = row * SM_ROW + (((row >> 3) & 1u) << 3)
                                   + (uint32_t)(idx & 7) * 8;
                CP_ASYNC8(dA + off, gA + (size_t)idx * 8);
                CP_ASYNC8(dB + off, gB + (size_t)idx * 8);
            }
            CP_COMMIT();
        };

        issueD(0); issueD(1);

        const uint32_t aswz = (uint32_t)rg * 8u;              // rows dw*16+rg*8+i
        const uint32_t bswz = (uint32_t)((cg >> 3) & 1) * 8u; // rows cg+16*j

#pragma unroll 1
        for (int kd = 0; kd < KS_D; kd++) {
            CP_WAIT1();
            BAR_D();
            if (kd + 2 < KS_D) issueD(kd + 2); else CP_COMMIT();

            const uint32_t ast = dbase + (kd % 3) * SM_STAGE;
            const uint32_t arow = ast + (uint32_t)(dw * 16 + rg * 8) * SM_ROW + aswz;
            const uint32_t brow = ast + SM_TILE + (uint32_t)cg * SM_ROW + bswz;
#pragma unroll
            for (int kb = 0; kb < 8; kb++) {
                uint32_t a0[8], a1[8];
#pragma unroll
                for (int i = 0; i < 8; i++)
                    LDS64(a0[i], a1[i], arow + i * SM_ROW + kb * 8);
                // j-loop split in halves of 4: caps live B regs, RF headroom
#pragma unroll
                for (int jh = 0; jh < 2; jh++) {
                    uint32_t b0[4], b1[4];
#pragma unroll
                    for (int j2 = 0; j2 < 4; j2++)
                        LDS64(b0[j2], b1[j2],
                              brow + (uint32_t)((jh * 4 + j2) * 16) * SM_ROW + kb * 8);
#pragma unroll
                    for (int i = 0; i < 8; i++)
#pragma unroll
                        for (int j2 = 0; j2 < 4; j2++)
                            acc[i][jh * 4 + j2] =
                                __dp4a((int)a1[i], (int)b1[j2],
                                __dp4a((int)a0[i], (int)b0[j2], acc[i][jh * 4 + j2]));
                }
            }
        }

        __syncthreads();   // wait for cbuf from tensor group

        // merge dp4a partials into cbuf (each element owned by one thread)
#pragma unroll
        for (int i = 0; i < 8; i++) {
            const int rl = dw * 16 + rg * 8 + i;
#pragma unroll
            for (int j = 0; j < 8; j++)
                cbuf[rl * 132 + cg + 16 * j] += acc[i][j];
        }
        __syncthreads();   // totals + rowbuf ready for everyone
    }

    // ================== epilogue: all 512 threads ===========================
    const int swp = g_swapsz;
    const float* scv = swp ? in3 : in2;   // true scales
    const float* zrv = swp ? in2 : in3;   // true zeros

    // col is loop-invariant per thread: e&127 == tid&127 (512 % 128 == 0)
    const int cc = tid & 127;
    const int c0 = tid >> 7;              // 0..3
    const int col = nt * 128 + cc;
    const float sc = scv[col];
    const float zr = zrv[col];
    const float wr = g_wrs[col];
    float* ocol = out + (size_t)(mt * 128) * QN + col;

#pragma unroll 4
    for (int j = 0; j < 32; j++) {
        const int r = 4 * j + c0;
        const float ts = rowp[r];
        const float zp = rowp[128 + r];
        const float A1 = rowp[256 + r];
        const float tot = (float)cbuf[r * 132 + cc];
        ocol[(size_t)r * QN] = ts * sc * (tot - zp * wr - zr * A1);
    }
}

// ================= launch ===================================================
extern "C" void kernel_launch(void* const* d_in, const int* in_sizes, int n_in,
                              void* d_out, int out_size) {
    const float* x    = (const float*)d_in[0];
    const void*  wbuf = d_in[1];
    const float* in2  = (const float*)d_in[2];
    const float* in3  = (const float*)d_in[3];
    float* out = (float*)d_out;

    cudaFuncSetAttribute(gemm_kernel, cudaFuncAttributeMaxDynamicSharedMemorySize,
                         (int)SMEM_TOTAL);

    detect_kernel<<<1, 256>>>((const uint32_t*)wbuf, in2);
    quant_kernel<<<QM, 256>>>(x);
    wprep_kernel<<<QN, 256>>>(wbuf);
    gemm_kernel<<<(QM / 128) * (QN / 128), 512, SMEM_TOTAL>>>(in2, in3, out);
}

// round 16
// speedup vs baseline: 1.1272x; 1.0873x over previous
#include <cuda_runtime.h>
#include <cstdint>

#define QM 8192
#define QK 4096
#define QN 4096

// GEMM: CTA 128x64, 256 threads, 2 CTAs/SM (occupancy = latency hiding).
// Warps 4-7: IMMA over K-stages [0,KS_T). Warps 0-3: dp4a over [KS_T,64).
// Per-stage costs halve together vs R12 -> keep measured 33/31 split.
#define KS_T 33
#define KS_D (64 - KS_T)

#define TILE_BYTES 8192u          // 128 rows x 64B per (tile, k-stage) block
#define SM_ROW 80u                // smem row stride
#define A_SM (128u * SM_ROW)      // 10240
#define B_SM (64u * SM_ROW)       // 5120
#define SM_STAGE (A_SM + B_SM)    // 15360
#define RINGT_BYTES (4u * SM_STAGE)              // 61440 (holds cbuf + rowbuf)
#define SMEM_TOTAL (RINGT_BYTES + 3u * SM_STAGE) // 107520 -> 2 CTAs/SM
#define ROWBUF_OFF 34816u         // after cbuf (128*68*4), inside ring-T space

// ---------------- device scratch (static allocation is allowed) -------------
__device__ __align__(256) int8_t g_A[(size_t)QM * QK];
__device__ __align__(256) int8_t g_B[(size_t)QN * QK];
__device__ float g_ts[QM];
__device__ float g_zp[QM];
__device__ float g_qsum[QM];
__device__ float g_wrs[QN];
__device__ int g_wmode;    // 0 = int8 buffer, 1 = int32 buffer, 2 = float32 buffer
__device__ int g_swapsz;   // 1 if d_in[2] actually holds zeros (swapped)

// ---------------- PTX helpers ----------------------------------------------
__device__ __forceinline__ uint32_t smem_u32(const void* p) {
    uint32_t a;
    asm("{ .reg .u64 t; cvta.to.shared.u64 t, %1; cvt.u32.u64 %0, t; }"
        : "=r"(a) : "l"(p));
    return a;
}

#define CP_ASYNC16(dst, src) \
    asm volatile("cp.async.cg.shared.global [%0], [%1], 16;" \
                 :: "r"(dst), "l"(src) : "memory")
#define CP_ASYNC8(dst, src) \
    asm volatile("cp.async.ca.shared.global [%0], [%1], 8;" \
                 :: "r"(dst), "l"(src) : "memory")
#define CP_COMMIT() asm volatile("cp.async.commit_group;" ::: "memory")
#define CP_WAIT2()  asm volatile("cp.async.wait_group 2;" ::: "memory")
#define CP_WAIT1()  asm volatile("cp.async.wait_group 1;" ::: "memory")

#define LDS64(r0, r1, a) \
    asm volatile("ld.shared.v2.u32 {%0,%1}, [%2];" : "=r"(r0), "=r"(r1) : "r"(a))

#define LDSM4(r0, r1, r2, r3, a) \
    asm volatile("ldmatrix.sync.aligned.m8n8.x4.shared.b16 {%0,%1,%2,%3}, [%4];" \
        : "=r"(r0), "=r"(r1), "=r"(r2), "=r"(r3) : "r"(a))

#define BAR_T() asm volatile("bar.sync 1, 128;" ::: "memory")
#define BAR_D() asm volatile("bar.sync 2, 128;" ::: "memory")

#define IMMA(c, a, b) \
    asm volatile("mma.sync.aligned.m16n8k32.row.col.s32.s8.s8.s32 " \
        "{%0,%1,%2,%3}, {%4,%5,%6,%7}, {%8,%9}, {%0,%1,%2,%3};" \
        : "+r"((c)[0]), "+r"((c)[1]), "+r"((c)[2]), "+r"((c)[3]) \
        : "r"((a)[0]), "r"((a)[1]), "r"((a)[2]), "r"((a)[3]), \
          "r"((b)[0]), "r"((b)[1]))

// ================= kernel 0: input-format detection =========================
__global__ void __launch_bounds__(256) detect_kernel(const uint32_t* __restrict__ w,
                                                     const float* __restrict__ p2) {
    __shared__ int not_i32, not_f32, p2_bad;
    if (threadIdx.x == 0) { not_i32 = 0; not_f32 = 0; p2_bad = 0; }
    __syncthreads();
    int ni = 0, nf = 0;
    for (int i = threadIdx.x; i < 4096; i += 256) {
        const uint32_t u = w[i];
        const int v = (int)u;
        if (!(v >= -128 && v <= 127)) ni++;
        const float f = __uint_as_float(u);
        if (!(isfinite(f) && fabsf(f) <= 128.0f && f == rintf(f))) nf++;
    }
    if (ni) atomicAdd(&not_i32, ni);
    if (nf) atomicAdd(&not_f32, nf);
    {
        const float s = p2[threadIdx.x * 16];
        if (!(s > 0.0f && s < 0.03f)) atomicAdd(&p2_bad, 1);
    }
    __syncthreads();
    if (threadIdx.x == 0) {
        g_wmode = (not_i32 == 0) ? 1 : ((not_f32 == 0) ? 2 : 0);
        g_swapsz = (p2_bad > 0) ? 1 : 0;
    }
}

// ================= kernel 1: per-token dynamic quant ========================
__device__ __forceinline__ int q_one(float v, float scale, float zp) {
    float t = rintf(__fdiv_rn(v, scale)) + zp;
    t = fminf(fmaxf(t, -128.0f), 127.0f);
    return (int)t;
}

__global__ void __launch_bounds__(256) quant_kernel(const float* __restrict__ x) {
    const int m = blockIdx.x;
    const int tid = threadIdx.x;
    const int lane = tid & 31, wid = tid >> 5;

    const float4* xr = reinterpret_cast<const float4*>(x) + (size_t)m * (QK / 4);
    float4 v[4];
    float mn = 0.0f, mx = 0.0f;
#pragma unroll
    for (int i = 0; i < 4; i++) {
        v[i] = xr[i * 256 + tid];
        mn = fminf(mn, fminf(fminf(v[i].x, v[i].y), fminf(v[i].z, v[i].w)));
        mx = fmaxf(mx, fmaxf(fmaxf(v[i].x, v[i].y), fmaxf(v[i].z, v[i].w)));
    }
#pragma unroll
    for (int o = 16; o; o >>= 1) {
        mn = fminf(mn, __shfl_xor_sync(0xffffffffu, mn, o));
        mx = fmaxf(mx, __shfl_xor_sync(0xffffffffu, mx, o));
    }
    __shared__ float smn[8], smx[8], s_scale, s_zp;
    __shared__ int s_qs;
    if (lane == 0) { smn[wid] = mn; smx[wid] = mx; }
    __syncthreads();
    if (tid == 0) {
        float a = smn[0], b = smx[0];
#pragma unroll
        for (int i = 1; i < 8; i++) { a = fminf(a, smn[i]); b = fmaxf(b, smx[i]); }
        float scale = fmaxf(__fdiv_rn(b - a, 255.0f), 1.1920928955078125e-07f);
        float zp = fminf(fmaxf(-128.0f - rintf(__fdiv_rn(a, scale)), -128.0f), 127.0f);
        s_scale = scale; s_zp = zp; s_qs = 0;
        g_ts[m] = scale;
        g_zp[m] = zp;
    }
    __syncthreads();
    const float scale = s_scale, zp = s_zp;
    int qs = 0;
    const size_t mtbase = (size_t)(m >> 7) * 64 * TILE_BYTES + (size_t)(m & 127) * 64;
#pragma unroll
    for (int i = 0; i < 4; i++) {
        const int k = (i * 256 + tid) * 4;
        int q0 = q_one(v[i].x, scale, zp);
        int q1 = q_one(v[i].y, scale, zp);
        int q2 = q_one(v[i].z, scale, zp);
        int q3 = q_one(v[i].w, scale, zp);
        qs += q0 + q1 + q2 + q3;
        char4 c4 = make_char4((char)q0, (char)q1, (char)q2, (char)q3);
        size_t pos = mtbase + (size_t)(k >> 6) * TILE_BYTES + (size_t)(k & 63);
        *reinterpret_cast<char4*>(g_A + pos) = c4;
    }
#pragma unroll
    for (int o = 16; o; o >>= 1) qs += __shfl_xor_sync(0xffffffffu, qs, o);
    if (lane == 0) atomicAdd(&s_qs, qs);
    __syncthreads();
    if (tid == 0) g_qsum[m] = (float)s_qs;
}

// ================= kernel 2: weight pre-tiling + row sums ===================
__global__ void __launch_bounds__(256) wprep_kernel(const void* __restrict__ wbuf) {
    const int o = blockIdx.x, tid = threadIdx.x;
    const int lane = tid & 31, wid = tid >> 5;
    const int mode = g_wmode;

    int4 v;
    if (mode == 0) {
        v = reinterpret_cast<const int4*>(wbuf)[(size_t)o * 256 + tid];
    } else {
        char tmp[16];
        if (mode == 1) {
            const int* p = reinterpret_cast<const int*>(wbuf) + (size_t)o * QK + tid * 16;
#pragma unroll
            for (int j = 0; j < 16; j++) tmp[j] = (char)p[j];
        } else {
            const float* p = reinterpret_cast<const float*>(wbuf) + (size_t)o * QK + tid * 16;
#pragma unroll
            for (int j = 0; j < 16; j++) tmp[j] = (char)(int)p[j];
        }
        v = *reinterpret_cast<const int4*>(tmp);
    }

    int s = 0;
    s = __dp4a(v.x, 0x01010101, s);
    s = __dp4a(v.y, 0x01010101, s);
    s = __dp4a(v.z, 0x01010101, s);
    s = __dp4a(v.w, 0x01010101, s);
    size_t pos = ((size_t)(o >> 7) * 64 + (size_t)(tid >> 2)) * TILE_BYTES
               + (size_t)(o & 127) * 64 + (size_t)(tid & 3) * 16;
    *reinterpret_cast<int4*>(g_B + pos) = v;

    __shared__ int sw[8];
#pragma unroll
    for (int t = 16; t; t >>= 1) s += __shfl_xor_sync(0xffffffffu, s, t);
    if (lane == 0) sw[wid] = s;
    __syncthreads();
    if (tid == 0) {
        int tot = 0;
#pragma unroll
        for (int i = 0; i < 8; i++) tot += sw[i];
        g_wrs[o] = (float)tot;
    }
}

// ================= kernel 3: hybrid IMMA + dp4a GEMM (128x64, occ 2) ========
__global__ void __launch_bounds__(256, 2)
gemm_kernel(const float* __restrict__ in2, const float* __restrict__ in3,
            float* __restrict__ out) {
    extern __shared__ __align__(128) char smem[];
    const uint32_t sbase = smem_u32(smem);
    const uint32_t dbase = sbase + RINGT_BYTES;
    const int tid = threadIdx.x;
    const int lane = tid & 31, wid = tid >> 5;
    const int nt = blockIdx.x & 63;   // n fastest -> wave reuses A tiles in L2
    const int mt = blockIdx.x >> 6;

    int* cbuf = reinterpret_cast<int*>(smem);   // 128 x 68 ints, in ring-T space
    float* rowp = reinterpret_cast<float*>(smem + ROWBUF_OFF); // [ts|zp|A1] x128

    // B tile (64 rows) lives inside a 128-row scratch block:
    const size_t gB_blk = (size_t)(nt >> 1) * 64;     // scratch block row-tile
    const size_t gB_sub = (size_t)(nt & 1) * 4096;    // 64-row half offset

    if (wid >= 4) {
        // ====== tensor group: warps 4-7, K-stages [0, KS_T) =================
        const int tw = wid - 4;
        const int wm = tw >> 1, wn = tw & 1;
        const int rr = lane >> 2, q = lane & 3;
        const int t2 = tid - 128;        // 0..127

        const uint32_t lsm_off = (uint32_t)(lane & 15) * SM_ROW
                               + (uint32_t)(lane >> 4) * 16u;

        int c[4][4][4];
#pragma unroll
        for (int mi = 0; mi < 4; mi++)
#pragma unroll
            for (int ni = 0; ni < 4; ni++)
#pragma unroll
                for (int r = 0; r < 4; r++) c[mi][ni][r] = 0;

        auto issueT = [&](int ks) {
            const int s = ks & 3;
            const int8_t* gA = g_A + ((size_t)(mt * 64 + ks)) * TILE_BYTES;
            const int8_t* gB = g_B + (gB_blk + (size_t)ks) * TILE_BYTES + gB_sub;
            const uint32_t dA = sbase + s * SM_STAGE;
            const uint32_t dB = dA + A_SM;
#pragma unroll
            for (int i = 0; i < 4; i++) {         // A: 512 chunks / 128 thr
                const int idx = t2 + i * 128;
                const uint32_t off = (uint32_t)(idx >> 2) * SM_ROW
                                   + (uint32_t)(idx & 3) * 16;
                CP_ASYNC16(dA + off, gA + (size_t)idx * 16);
            }
#pragma unroll
            for (int i = 0; i < 2; i++) {         // B: 256 chunks / 128 thr
                const int idx = t2 + i * 128;
                const uint32_t off = (uint32_t)(idx >> 2) * SM_ROW
                                   + (uint32_t)(idx & 3) * 16;
                CP_ASYNC16(dB + off, gB + (size_t)idx * 16);
            }
            CP_COMMIT();
        };

        issueT(0); issueT(1); issueT(2);

#pragma unroll 1
        for (int ks = 0; ks < KS_T; ks++) {
            CP_WAIT2();
            BAR_T();
            if (ks + 3 < KS_T) issueT(ks + 3); else CP_COMMIT();

            const uint32_t ast = sbase + (ks & 3) * SM_STAGE;
            const uint32_t bst = ast + A_SM;
#pragma unroll
            for (int kj = 0; kj < 2; kj++) {
                uint32_t a[4][4], b[4][2];
#pragma unroll
                for (int mi = 0; mi < 4; mi++)
                    LDSM4(a[mi][0], a[mi][1], a[mi][2], a[mi][3],
                          ast + (uint32_t)(wm * 64 + mi * 16) * SM_ROW
                              + (uint32_t)(kj * 32) + lsm_off);
                LDSM4(b[0][0], b[1][0], b[0][1], b[1][1],
                      bst + (uint32_t)(wn * 32) * SM_ROW
                          + (uint32_t)(kj * 32) + lsm_off);
                LDSM4(b[2][0], b[3][0], b[2][1], b[3][1],
                      bst + (uint32_t)(wn * 32 + 16) * SM_ROW
                          + (uint32_t)(kj * 32) + lsm_off);
#pragma unroll
                for (int mi = 0; mi < 4; mi++)
#pragma unroll
                    for (int ni = 0; ni < 4; ni++)
                        IMMA(c[mi][ni], a[mi], b[ni]);
            }
        }

        // done reading ring T -> safe to overwrite with cbuf
        BAR_T();
#pragma unroll
        for (int mi = 0; mi < 4; mi++)
#pragma unroll
            for (int half = 0; half < 2; half++) {
                const int rl = wm * 64 + mi * 16 + rr + half * 8;
#pragma unroll
                for (int ni = 0; ni < 4; ni++) {
                    const int cl = wn * 32 + ni * 8 + q * 2;
                    cbuf[rl * 68 + cl]     = c[mi][ni][half * 2 + 0];
                    cbuf[rl * 68 + cl + 1] = c[mi][ni][half * 2 + 1];
                }
            }
        __syncthreads();   // hand cbuf to dp4a group

        // stage row params for epilogue (128 tensor threads, 128 rows)
        {
            const int row = mt * 128 + t2;
            const float ts = g_ts[row];
            const float zp = g_zp[row];
            rowp[t2]       = ts;
            rowp[128 + t2] = zp;
            rowp[256 + t2] = g_qsum[row] - 4096.0f * zp;
        }
        __syncthreads();   // wait for dp4a partials merged + rowbuf visible
    } else {
        // ========= dp4a group: warps 0-3, K-stages [KS_T, 64) ===============
        // smem rows swizzled: row r at r*80 + 8*((r>>3)&1) (conflict-free)
        const int dw = wid;               // 0..3 -> rows dw*32 .. dw*32+31
        const int rg = lane >> 4;         // 0..1 (rows 8 apart across rg!)
        const int cg = lane & 15;         // cols cg + 16*j, j<4

        int acc[16][4];
#pragma unroll
        for (int i = 0; i < 16; i++)
#pragma unroll
            for (int j = 0; j < 4; j++) acc[i][j] = 0;

        auto issueD = [&](int kd) {
            const int s = kd % 3;
            const int ks = KS_T + kd;
            const int8_t* gA = g_A + ((size_t)(mt * 64 + ks)) * TILE_BYTES;
            const int8_t* gB = g_B + (gB_blk + (size_t)ks) * TILE_BYTES + gB_sub;
            const uint32_t dA = dbase + s * SM_STAGE;
            const uint32_t dB = dA + A_SM;
#pragma unroll
            for (int i = 0; i < 8; i++) {        // A: 1024 8B-chunks / 128 thr
                const int idx = tid + i * 128;
                const uint32_t row = (uint32_t)(idx >> 3);
                const uint32_t off = row * SM_ROW + (((row >> 3) & 1u) << 3)
                                   + (uint32_t)(idx & 7) * 8;
                CP_ASYNC8(dA + off, gA + (size_t)idx * 8);
            }
#pragma unroll
            for (int i = 0; i < 4; i++) {        // B: 512 8B-chunks / 128 thr
                const int idx = tid + i * 128;
                const uint32_t row = (uint32_t)(idx >> 3);
                const uint32_t off = row * SM_ROW + (((row >> 3) & 1u) << 3)
                                   + (uint32_t)(idx & 7) * 8;
                CP_ASYNC8(dB + off, gB + (size_t)idx * 8);
            }
            CP_COMMIT();
        };

        issueD(0); issueD(1);

        const uint32_t aswz = (uint32_t)rg * 8u;              // rg rows 8 apart
        const uint32_t bswz = (uint32_t)((cg >> 3) & 1) * 8u; // rows cg+16*j

#pragma unroll 1
        for (int kd = 0; kd < KS_D; kd++) {
            CP_WAIT1();
            BAR_D();
            if (kd + 2 < KS_D) issueD(kd + 2); else CP_COMMIT();

            const uint32_t ast = dbase + (kd % 3) * SM_STAGE;
            // lane row i (i<16): dw*32 + (i>>3)*16 + rg*8 + (i&7)
            const uint32_t arow = ast + (uint32_t)(dw * 32 + rg * 8) * SM_ROW + aswz;
            const uint32_t brow = ast + A_SM + (uint32_t)cg * SM_ROW + bswz;
#pragma unroll
            for (int kb = 0; kb < 8; kb++) {
                uint32_t b0[4], b1[4];
#pragma unroll
                for (int j = 0; j < 4; j++)
                    LDS64(b0[j], b1[j],
                          brow + (uint32_t)(j * 16) * SM_ROW + kb * 8);
#pragma unroll
                for (int ih = 0; ih < 2; ih++) {   // row halves 16 apart
                    uint32_t a0[8], a1[8];
#pragma unroll
                    for (int i2 = 0; i2 < 8; i2++)
                        LDS64(a0[i2], a1[i2],
                              arow + (uint32_t)(ih * 16 + i2) * SM_ROW + kb * 8);
#pragma unroll
                    for (int i2 = 0; i2 < 8; i2++)
#pragma unroll
                        for (int j = 0; j < 4; j++)
                            acc[ih * 8 + i2][j] =
                                __dp4a((int)a1[i2], (int)b1[j],
                                __dp4a((int)a0[i2], (int)b0[j], acc[ih * 8 + i2][j]));
                }
            }
        }

        __syncthreads();   // wait for cbuf from tensor group

        // merge dp4a partials into cbuf (each element owned by one thread)
#pragma unroll
        for (int i = 0; i < 16; i++) {
            const int rl = dw * 32 + (i >> 3) * 16 + rg * 8 + (i & 7);
#pragma unroll
            for (int j = 0; j < 4; j++)
                cbuf[rl * 68 + cg + 16 * j] += acc[i][j];
        }
        __syncthreads();   // totals + rowbuf ready for everyone
    }

    // ================== epilogue: all 256 threads ===========================
    const int swp = g_swapsz;
    const float* scv = swp ? in3 : in2;   // true scales
    const float* zrv = swp ? in2 : in3;   // true zeros

    const int cc = tid & 63;              // 64 cols per tile
    const int c0 = tid >> 6;              // 0..3
    const int col = nt * 64 + cc;
    const float sc = scv[col];
    const float zr = zrv[col];
    const float wr = g_wrs[col];
    float* ocol = out + (size_t)(mt * 128) * QN + col;

#pragma unroll 4
    for (int j = 0; j < 32; j++) {
        const int r = 4 * j + c0;
        const float ts = rowp[r];
        const float zp = rowp[128 + r];
        const float A1 = rowp[256 + r];
        const float tot = (float)cbuf[r * 68 + cc];
        ocol[(size_t)r * QN] = ts * sc * (tot - zp * wr - zr * A1);
    }
}

// ================= launch ===================================================
extern "C" void kernel_launch(void* const* d_in, const int* in_sizes, int n_in,
                              void* d_out, int out_size) {
    const float* x    = (const float*)d_in[0];
    const void*  wbuf = d_in[1];
    const float* in2  = (const float*)d_in[2];
    const float* in3  = (const float*)d_in[3];
    float* out = (float*)d_out;

    cudaFuncSetAttribute(gemm_kernel, cudaFuncAttributeMaxDynamicSharedMemorySize,
                         (int)SMEM_TOTAL);

    detect_kernel<<<1, 256>>>((const uint32_t*)wbuf, in2);
    quant_kernel<<<QM, 256>>>(x);
    wprep_kernel<<<QN, 256>>>(wbuf);
    gemm_kernel<<<(QM / 128) * (QN / 64), 256, SMEM_TOTAL>>>(in2, in3, out);
}